// round 2
// baseline (speedup 1.0000x reference)
#include <cuda_runtime.h>
#include <math.h>

#define N_EDGES_C 100000
#define WNUM_C 2304
// smem: 16*2304 fc2 floats + 160 fc1 floats
#define SMEM_FLOATS (16 * 2304 + 160)
#define SMEM_BYTES (SMEM_FLOATS * 4)

// C0 = C1 = C2 = 1/sqrt(48), C3 = 0.25 (derived from MUL_S=32, MUL_V=16)
#define C0F 0.14433756729740643f
#define C1F 0.14433756729740643f
#define C2F 0.14433756729740643f
#define C3F 0.25f

typedef unsigned long long u64;

__device__ __forceinline__ u64 pack2(float x) {
    u64 r; asm("mov.b64 %0, {%1, %1};" : "=l"(r) : "f"(x)); return r;
}
__device__ __forceinline__ void fma2(u64 &acc, u64 w, u64 f) {
    asm("fma.rn.f32x2 %0, %1, %2, %0;" : "+l"(acc) : "l"(w), "l"(f));
}
__device__ __forceinline__ float2 unpack2(u64 v) {
    float2 r; asm("mov.b64 {%0, %1}, %2;" : "=f"(r.x), "=f"(r.y) : "l"(v)); return r;
}

__global__ __launch_bounds__(512, 1)
void tp_fused2(const float* __restrict__ feature,
               const int*   __restrict__ edge,
               const float* __restrict__ ele,
               const float* __restrict__ esh,
               const float* __restrict__ fw1,
               const float* __restrict__ fw2,
               float*       __restrict__ out,
               float silu_c)
{
    extern __shared__ float smem[];
    float* sW  = smem;             // [16][2304] normalized fc_w2 (x0.25)
    float* sW1 = smem + 16 * 2304; // [10][16]  normalized fc_w1 (x 1/sqrt(10))

    // ---- stage weights into shared ----
    {
        const float4* src = (const float4*)fw2;
        float4* dst = (float4*)sW;
        for (int i = threadIdx.x; i < (16 * 2304) / 4; i += blockDim.x) {
            float4 v = src[i];
            v.x *= 0.25f; v.y *= 0.25f; v.z *= 0.25f; v.w *= 0.25f;
            dst[i] = v;
        }
        const float inb = 0.31622776601683794f; // 1/sqrt(10)
        for (int i = threadIdx.x; i < 160; i += blockDim.x)
            sW1[i] = fw1[i] * inb;
    }
    __syncthreads();

    const int lane   = threadIdx.x & 31;
    const int warp   = threadIdx.x >> 5;
    const int gwarp  = blockIdx.x * 16 + warp;
    const int nwarps = gridDim.x * 16;
    const int half   = lane & 1;   // which half of output channels
    const int epos   = lane >> 1;  // edge slot within 16-edge chunk
    const int nchunks = N_EDGES_C / 16; // 6250

    for (int c = gwarp; c < nchunks; c += nwarps) {
        const int e = c * 16 + epos;

        // ---- h = silu_c * silu(ele @ fc_w1n) ----
        float h[16];
        {
            float x[10];
            const float* er = ele + e * 10;
            #pragma unroll
            for (int j = 0; j < 10; j++) x[j] = er[j];
            #pragma unroll
            for (int k = 0; k < 16; k++) {
                float a = 0.f;
                #pragma unroll
                for (int j = 0; j < 10; j++) a = fmaf(x[j], sW1[j * 16 + k], a);
                float sg = 1.0f / (1.0f + __expf(-a));
                h[k] = silu_c * a * sg;
            }
        }

        const int dst = edge[N_EDGES_C + e]; // edge[1][e]
        const float* frow = feature + (size_t)dst * 80;
        const float4 shv  = ((const float4*)esh)[e];
        const float s2 = shv.x, v2x = shv.y, v2y = shv.z, v2z = shv.w;

        // =========== Pass A: r0 (W0,s1) and t1 (W1,s1) — this lane's half ===========
        float s1[32];
        #pragma unroll
        for (int q = 0; q < 8; q++) {
            float4 f4 = ((const float4*)frow)[q];
            s1[q*4+0] = f4.x; s1[q*4+1] = f4.y; s1[q*4+2] = f4.z; s1[q*4+3] = f4.w;
        }
        u64 r0p[8], t1p[4];
        #pragma unroll
        for (int q = 0; q < 8; q++) r0p[q] = 0ull;
        #pragma unroll
        for (int q = 0; q < 4; q++) t1p[q] = 0ull;

        const float* baseW0 = sW + half * 16;         // W0[k][u][half*16 ..]
        const float* baseW1 = sW + 1024 + half * 8;   // W1[k][u][half*8 ..]

        #pragma unroll 1
        for (int k = 0; k < 16; k++) {
            const float hk = h[k];
            const float* W0k = baseW0 + k * WNUM_C;
            const float* W1k = baseW1 + k * WNUM_C;
            #pragma unroll 4
            for (int u = 0; u < 32; u++) {
                u64 ff = pack2(hk * s1[u]);
                const ulonglong2* c0 = (const ulonglong2*)(W0k + u * 32);
                #pragma unroll
                for (int q = 0; q < 4; q++) {
                    ulonglong2 wv = c0[q];
                    fma2(r0p[q*2+0], wv.x, ff);
                    fma2(r0p[q*2+1], wv.y, ff);
                }
                const ulonglong2* c1 = (const ulonglong2*)(W1k + u * 16);
                #pragma unroll
                for (int q = 0; q < 2; q++) {
                    ulonglong2 wv = c1[q];
                    fma2(t1p[q*2+0], wv.x, ff);
                    fma2(t1p[q*2+1], wv.y, ff);
                }
            }
        }

        // partial out_s (this half): C0*s2*r0  (r3 term added in pass C)
        float* orow = out + (size_t)e * 80 + half * 16;
        {
            const float cs = C0F * s2;
            #pragma unroll
            for (int q = 0; q < 8; q++) {
                float2 v = unpack2(r0p[q]);
                float2 o; o.x = cs * v.x; o.y = cs * v.y;
                ((float2*)orow)[q] = o;
            }
        }

        // =========== Pass B: t2 (W2,v1) — outer u, inner k ===========
        u64 t2p[12]; // [i][4 pairs of w]
        #pragma unroll
        for (int q = 0; q < 12; q++) t2p[q] = 0ull;

        const float* baseW2 = sW + 1536 + half * 8;
        #pragma unroll 1
        for (int u = 0; u < 16; u++) {
            const float v1x = frow[32 + u*3 + 0];
            const float v1y = frow[32 + u*3 + 1];
            const float v1z = frow[32 + u*3 + 2];
            #pragma unroll 4
            for (int k = 0; k < 16; k++) {
                const float hk = h[k];
                u64 fx = pack2(hk * v1x);
                u64 fy = pack2(hk * v1y);
                u64 fz = pack2(hk * v1z);
                const ulonglong2* c2 = (const ulonglong2*)(baseW2 + k * WNUM_C + u * 16);
                #pragma unroll
                for (int q = 0; q < 2; q++) {
                    ulonglong2 wv = c2[q];
                    fma2(t2p[0 + q*2+0], wv.x, fx); fma2(t2p[0 + q*2+1], wv.y, fx);
                    fma2(t2p[4 + q*2+0], wv.x, fy); fma2(t2p[4 + q*2+1], wv.y, fy);
                    fma2(t2p[8 + q*2+0], wv.x, fz); fma2(t2p[8 + q*2+1], wv.y, fz);
                }
            }
        }

        // out_v[w,i] = C1*t1[w]*v2[i] + C2*s2*t2[w,i]  (this lane's 8 w's)
        {
            float t1v[8];
            #pragma unroll
            for (int q = 0; q < 4; q++) {
                float2 v = unpack2(t1p[q]);
                t1v[2*q] = v.x; t1v[2*q+1] = v.y;
            }
            float t2v[24]; // [i][8]
            #pragma unroll
            for (int i = 0; i < 3; i++) {
                #pragma unroll
                for (int q = 0; q < 4; q++) {
                    float2 v = unpack2(t2p[i*4+q]);
                    t2v[i*8 + 2*q] = v.x; t2v[i*8 + 2*q + 1] = v.y;
                }
            }
            const float c2s = C2F * s2;
            float ov[24];
            #pragma unroll
            for (int w = 0; w < 8; w++) {
                const float a = C1F * t1v[w];
                ov[w*3+0] = fmaf(a, v2x, c2s * t2v[0*8+w]);
                ov[w*3+1] = fmaf(a, v2y, c2s * t2v[1*8+w]);
                ov[w*3+2] = fmaf(a, v2z, c2s * t2v[2*8+w]);
            }
            float4* ovp = (float4*)(out + (size_t)e * 80 + 32 + half * 24);
            #pragma unroll
            for (int q = 0; q < 6; q++) {
                float4 o;
                o.x = ov[q*4+0]; o.y = ov[q*4+1]; o.z = ov[q*4+2]; o.w = ov[q*4+3];
                ovp[q] = o;
            }
        }

        // =========== Pass C: r3 (W3, v1.v2) — outer u, inner k ===========
        u64 r3p[8];
        #pragma unroll
        for (int q = 0; q < 8; q++) r3p[q] = 0ull;

        const float* baseW3 = sW + 1792 + half * 16;
        #pragma unroll 1
        for (int u = 0; u < 16; u++) {
            const float v1x = frow[32 + u*3 + 0];
            const float v1y = frow[32 + u*3 + 1];
            const float v1z = frow[32 + u*3 + 2];
            const float b = fmaf(v1x, v2x, fmaf(v1y, v2y, v1z * v2z));
            #pragma unroll 4
            for (int k = 0; k < 16; k++) {
                u64 ff = pack2(h[k] * b);
                const ulonglong2* c3 = (const ulonglong2*)(baseW3 + k * WNUM_C + u * 32);
                #pragma unroll
                for (int q = 0; q < 4; q++) {
                    ulonglong2 wv = c3[q];
                    fma2(r3p[q*2+0], wv.x, ff);
                    fma2(r3p[q*2+1], wv.y, ff);
                }
            }
        }

        // out_s += C3 * r3 (RMW of our own earlier write — same thread)
        #pragma unroll
        for (int q = 0; q < 8; q++) {
            float2 o = ((float2*)orow)[q];
            float2 v = unpack2(r3p[q]);
            o.x = fmaf(C3F, v.x, o.x);
            o.y = fmaf(C3F, v.y, o.y);
            ((float2*)orow)[q] = o;
        }
    }
}

// Replicates the reference's numerically-integrated silu normalization
// constant exactly (double-precision trapz on the same grid). Host-side,
// deterministic, not part of the timed graph body.
static float compute_silu_c()
{
    const int N = 200001;
    const double dx = 24.0 / 200000.0;
    const double inv_sqrt_2pi = 0.3989422804014326779;
    double acc = 0.0, prev = 0.0;
    for (int i = 0; i < N; i++) {
        double x = -12.0 + dx * (double)i;
        double pdf = exp(-0.5 * x * x) * inv_sqrt_2pi;
        double s = x / (1.0 + exp(-x));
        double y = s * s * pdf;
        if (i > 0) acc += 0.5 * (y + prev) * dx;
        prev = y;
    }
    return (float)(1.0 / sqrt(acc));
}

extern "C" void kernel_launch(void* const* d_in, const int* in_sizes, int n_in,
                              void* d_out, int out_size)
{
    const float* feature = (const float*)d_in[0];
    const int*   edge    = (const int*)  d_in[1];
    const float* ele     = (const float*)d_in[2];
    const float* esh     = (const float*)d_in[3];
    const float* fw1     = (const float*)d_in[4];
    const float* fw2     = (const float*)d_in[5];
    float* out = (float*)d_out;

    float silu_c = compute_silu_c();

    cudaFuncSetAttribute(tp_fused2,
                         cudaFuncAttributeMaxDynamicSharedMemorySize, SMEM_BYTES);

    tp_fused2<<<152, 512, SMEM_BYTES>>>(feature, edge, ele, esh, fw1, fw2,
                                        out, silu_c);
}

// round 3
// speedup vs baseline: 4.3033x; 4.3033x over previous
#include <cuda_runtime.h>
#include <cuda_fp16.h>
#include <math.h>

#define N_EDGES_C 100000
#define NTILES    (N_EDGES_C / 16)   // 6250 exact

// e3nn constants: C0=C1=C2=1/sqrt(48), C3=0.25
#define C0F 0.14433756729740643f
#define C1F 0.14433756729740643f
#define C2F 0.14433756729740643f
#define C3F 0.25f

// ---- smem layout (bytes) ----
#define SW1_OFF   0                      // 160 floats
#define BG_OFF    1024                   // uint2[32*6*32]  = 49152 B
#define BP_OFF    (BG_OFF + 49152)      // uint2[16*4*32]  = 16384 B
#define BQ_OFF    (BP_OFF + 16384)      // uint2[16*2*32]  =  8192 B
#define WS_OFF    (BQ_OFF + 8192)       // per-warp staging
#define WS_STRIDE 8320                   // bytes per warp (2080 floats)
// per-warp float offsets
#define H_F    0      // h[m*17+kh]        272
#define S1_F   272    // s1[m*36+u]        576
#define V1_F   848    // v1T[i*288+m*18+u] 864
#define B_F    1712   // b[m*18+u]         288
#define S2_F   2000   // s2[m]             16
#define V2_F   2016   // v2[m*3+i]         48
#define DST_F  2064   // dst[m] (int)      16
#define SMEM_TOTAL (WS_OFF + 16 * WS_STRIDE)   // 207,872 B

__device__ unsigned int g_ticket;

__global__ void zero_ticket_k() { g_ticket = 0u; }

__device__ __forceinline__ unsigned packh(float lo, float hi) {
    unsigned r;
    asm("cvt.rn.f16x2.f32 %0, %1, %2;" : "=r"(r) : "f"(hi), "f"(lo));
    return r;
}
__device__ __forceinline__ void mma16816(float* d,
    unsigned a0, unsigned a1, unsigned a2, unsigned a3,
    unsigned b0, unsigned b1)
{
    asm volatile(
      "mma.sync.aligned.m16n8k16.row.col.f32.f16.f16.f32 "
      "{%0,%1,%2,%3},{%4,%5,%6,%7},{%8,%9},{%0,%1,%2,%3};"
      : "+f"(d[0]), "+f"(d[1]), "+f"(d[2]), "+f"(d[3])
      : "r"(a0), "r"(a1), "r"(a2), "r"(a3), "r"(b0), "r"(b1));
}

__global__ __launch_bounds__(512, 1)
void tp_mma_kernel(const float* __restrict__ feature,
                   const int*   __restrict__ edge,
                   const float* __restrict__ ele,
                   const float* __restrict__ esh,
                   const float* __restrict__ fw1,
                   const float* __restrict__ fw2,
                   float*       __restrict__ out,
                   float silu_c)
{
    extern __shared__ char smem[];
    float* sW1      = (float*)(smem + SW1_OFF);
    uint2* Bg       = (uint2*)(smem + BG_OFF);
    uint2* Bp       = (uint2*)(smem + BP_OFF);
    uint2* Bq       = (uint2*)(smem + BQ_OFF);

    const int tid  = threadIdx.x;
    const int lane = tid & 31;
    const int warp = tid >> 5;
    const int gq   = lane >> 2;   // fragment "group" = row 0..7
    const int t    = lane & 3;    // fragment thread-in-group

    // ================= prologue: stage fc_w1 + fragment-major B ================
    {
        const float inb = 0.31622776601683794f; // 1/sqrt(10)
        for (int i = tid; i < 160; i += 512) sW1[i] = fw1[i] * inb;

        // Bg: 6144 entries, Bp: 2048, Bq: 1024 (uint2 each = 4 fp16 B values)
        for (int i = tid; i < 6144 + 2048 + 1024; i += 512) {
            int li = i & 31;           // lane slot
            int gg = li >> 2, tt = li & 3;
            int mmaid = i >> 5;        // which mma
            float v0, v1, v2, v3;
            if (i < 6144) {            // Bg: [kc<32][nb<6]
                int kc = mmaid / 6, nb = mmaid % 6;
                int c = nb * 8 + gg, k0 = kc * 16;
                int ks[4] = {k0 + 2*tt, k0 + 2*tt + 1, k0 + 2*tt + 8, k0 + 2*tt + 9};
                float vv[4];
                #pragma unroll
                for (int j = 0; j < 4; j++) {
                    int k = ks[j], kh = k >> 5, u = k & 31;
                    vv[j] = 0.25f * (c < 32
                          ? fw2[kh * 2304 + u * 32 + c]
                          : fw2[kh * 2304 + 1024 + u * 16 + (c - 32)]);
                }
                v0 = vv[0]; v1 = vv[1]; v2 = vv[2]; v3 = vv[3];
                Bg[i] = make_uint2(packh(v0, v1), packh(v2, v3));
            } else if (i < 6144 + 2048) { // Bp: [kc<16][nb<4], W3 block
                int ii = i - 6144;
                int mm = ii >> 5;
                int kc = mm / 4, nb = mm % 4;
                int c = nb * 8 + gg, k0 = kc * 16;
                int ks[4] = {k0 + 2*tt, k0 + 2*tt + 1, k0 + 2*tt + 8, k0 + 2*tt + 9};
                float vv[4];
                #pragma unroll
                for (int j = 0; j < 4; j++) {
                    int k = ks[j], kh = k >> 4, u = k & 15;
                    vv[j] = 0.25f * fw2[kh * 2304 + 1792 + u * 32 + c];
                }
                Bp[ii] = make_uint2(packh(vv[0], vv[1]), packh(vv[2], vv[3]));
            } else {                   // Bq: [kc<16][nb<2], W2 block
                int ii = i - 6144 - 2048;
                int mm = ii >> 5;
                int kc = mm / 2, nb = mm % 2;
                int c = nb * 8 + gg, k0 = kc * 16;
                int ks[4] = {k0 + 2*tt, k0 + 2*tt + 1, k0 + 2*tt + 8, k0 + 2*tt + 9};
                float vv[4];
                #pragma unroll
                for (int j = 0; j < 4; j++) {
                    int k = ks[j], kh = k >> 4, u = k & 15;
                    vv[j] = 0.25f * fw2[kh * 2304 + 1536 + u * 16 + c];
                }
                Bq[ii] = make_uint2(packh(vv[0], vv[1]), packh(vv[2], vv[3]));
            }
        }
    }
    __syncthreads();

    float* ws = (float*)(smem + WS_OFF + warp * WS_STRIDE);
    int*   wsd = (int*)(ws + DST_F);

    // ================= per-warp tile loop (atomic ticket) ================
    for (;;) {
        unsigned tile;
        if (lane == 0) tile = atomicAdd(&g_ticket, 1u);
        tile = __shfl_sync(0xFFFFFFFFu, tile, 0);
        if (tile >= NTILES) break;
        const int e0 = (int)tile * 16;

        // ---- stage esh + dst ----
        if (lane < 16) {
            float4 q4 = ((const float4*)esh)[e0 + lane];
            ws[S2_F + lane] = q4.x;
            ws[V2_F + lane * 3 + 0] = q4.y;
            ws[V2_F + lane * 3 + 1] = q4.z;
            ws[V2_F + lane * 3 + 2] = q4.w;
            wsd[lane] = edge[N_EDGES_C + e0 + lane];
        }
        __syncwarp();

        // ---- h: lane computes 8 of 256 values ----
        {
            int m = lane & 15, half = lane >> 4;
            const float2* er2 = (const float2*)(ele + (size_t)(e0 + m) * 10);
            float x[10];
            #pragma unroll
            for (int j = 0; j < 5; j++) { float2 v = er2[j]; x[2*j] = v.x; x[2*j+1] = v.y; }
            #pragma unroll
            for (int j = 0; j < 8; j++) {
                int kh = half * 8 + j;
                float a = 0.f;
                #pragma unroll
                for (int r = 0; r < 10; r++) a = fmaf(x[r], sW1[r * 16 + kh], a);
                float sg = 1.0f / (1.0f + __expf(-a));
                ws[H_F + m * 17 + kh] = silu_c * a * sg;
            }
        }

        // ---- feature gather: s1 + v1T ----
        #pragma unroll 1
        for (int m = 0; m < 16; m++) {
            const float2* fr = (const float2*)(feature + (size_t)wsd[m] * 80);
            float2 f = fr[lane];
            int el = 2 * lane;
            #pragma unroll
            for (int pz = 0; pz < 2; pz++) {
                int ee = el + pz;
                float vv = pz ? f.y : f.x;
                if (ee < 32) ws[S1_F + m * 36 + ee] = vv;
                else { int j = ee - 32; ws[V1_F + (j % 3) * 288 + m * 18 + j / 3] = vv; }
            }
            if (lane < 8) {
                float2 f2 = fr[32 + lane];
                int j0 = 64 + 2 * lane - 32;
                ws[V1_F + (j0 % 3) * 288 + m * 18 + j0 / 3] = f2.x;
                int j1 = j0 + 1;
                ws[V1_F + (j1 % 3) * 288 + m * 18 + j1 / 3] = f2.y;
            }
        }
        __syncwarp();

        // ---- b[m][u] = v1[m][u] . v2[m] ----
        {
            int m = lane >> 1, u0b = (lane & 1) * 8;
            float w2x = ws[V2_F + m * 3 + 0], w2y = ws[V2_F + m * 3 + 1], w2z = ws[V2_F + m * 3 + 2];
            #pragma unroll
            for (int j = 0; j < 8; j++) {
                int u = u0b + j;
                float bb = fmaf(ws[V1_F + 0 * 288 + m * 18 + u], w2x,
                           fmaf(ws[V1_F + 1 * 288 + m * 18 + u], w2y,
                                ws[V1_F + 2 * 288 + m * 18 + u] * w2z));
                ws[B_F + m * 18 + u] = bb;
            }
        }
        __syncwarp();

        // ================ GEMM phase 1: g = h (x) s1,  N=48 (R0|R1) ================
        float ag[6][4];
        #pragma unroll
        for (int nb = 0; nb < 6; nb++) { ag[nb][0]=0.f; ag[nb][1]=0.f; ag[nb][2]=0.f; ag[nb][3]=0.f; }

        #pragma unroll 2
        for (int kc = 0; kc < 32; kc++) {
            int kh = kc >> 1, u0 = (kc & 1) * 16;
            float h0 = ws[H_F + gq * 17 + kh];
            float h1 = ws[H_F + (gq + 8) * 17 + kh];
            const float2* s0 = (const float2*)(ws + S1_F + gq * 36 + u0);
            const float2* s1r = (const float2*)(ws + S1_F + (gq + 8) * 36 + u0);
            float2 xa = s0[t], xb = s0[t + 4];
            float2 ya = s1r[t], yb = s1r[t + 4];
            unsigned a0 = packh(h0 * xa.x, h0 * xa.y);
            unsigned a1 = packh(h1 * ya.x, h1 * ya.y);
            unsigned a2 = packh(h0 * xb.x, h0 * xb.y);
            unsigned a3 = packh(h1 * yb.x, h1 * yb.y);
            const uint2* bp = Bg + kc * 6 * 32 + lane;
            #pragma unroll
            for (int nb = 0; nb < 6; nb++) {
                uint2 bb = bp[nb * 32];
                mma16816(ag[nb], a0, a1, a2, a3, bb.x, bb.y);
            }
        }

        // ================ GEMM phase 2: p = h (x) b,  N=32 (R3) ================
        float ap[4][4];
        #pragma unroll
        for (int nb = 0; nb < 4; nb++) { ap[nb][0]=0.f; ap[nb][1]=0.f; ap[nb][2]=0.f; ap[nb][3]=0.f; }

        #pragma unroll 2
        for (int kc = 0; kc < 16; kc++) {
            float h0 = ws[H_F + gq * 17 + kc];
            float h1 = ws[H_F + (gq + 8) * 17 + kc];
            const float2* b0p = (const float2*)(ws + B_F + gq * 18);
            const float2* b1p = (const float2*)(ws + B_F + (gq + 8) * 18);
            float2 xa = b0p[t], xb = b0p[t + 4];
            float2 ya = b1p[t], yb = b1p[t + 4];
            unsigned a0 = packh(h0 * xa.x, h0 * xa.y);
            unsigned a1 = packh(h1 * ya.x, h1 * ya.y);
            unsigned a2 = packh(h0 * xb.x, h0 * xb.y);
            unsigned a3 = packh(h1 * yb.x, h1 * yb.y);
            const uint2* bp = Bp + kc * 4 * 32 + lane;
            #pragma unroll
            for (int nb = 0; nb < 4; nb++) {
                uint2 bb = bp[nb * 32];
                mma16816(ap[nb], a0, a1, a2, a3, bb.x, bb.y);
            }
        }

        // ---- epilogue part 1: out_s = C0*s2*R0 + C3*R3 ----
        {
            float s2_0 = ws[S2_F + gq], s2_1 = ws[S2_F + gq + 8];
            float* row0 = out + (size_t)(e0 + gq) * 80;
            float* row1 = out + (size_t)(e0 + gq + 8) * 80;
            #pragma unroll
            for (int nb = 0; nb < 4; nb++) {
                int w = nb * 8 + 2 * t;
                float2 o0, o1;
                o0.x = fmaf(C0F * s2_0, ag[nb][0], C3F * ap[nb][0]);
                o0.y = fmaf(C0F * s2_0, ag[nb][1], C3F * ap[nb][1]);
                o1.x = fmaf(C0F * s2_1, ag[nb][2], C3F * ap[nb][2]);
                o1.y = fmaf(C0F * s2_1, ag[nb][3], C3F * ap[nb][3]);
                *(float2*)(row0 + w) = o0;
                *(float2*)(row1 + w) = o1;
            }
        }

        // ================ GEMM phase 3: q_i = h (x) v1_i,  N=16 each (R2i) ================
        float aq[3][2][4];
        #pragma unroll
        for (int i = 0; i < 3; i++)
            #pragma unroll
            for (int nb = 0; nb < 2; nb++) { aq[i][nb][0]=0.f; aq[i][nb][1]=0.f; aq[i][nb][2]=0.f; aq[i][nb][3]=0.f; }

        #pragma unroll 1
        for (int i = 0; i < 3; i++) {
            #pragma unroll 2
            for (int kc = 0; kc < 16; kc++) {
                float h0 = ws[H_F + gq * 17 + kc];
                float h1 = ws[H_F + (gq + 8) * 17 + kc];
                const float2* v0p = (const float2*)(ws + V1_F + i * 288 + gq * 18);
                const float2* v1p = (const float2*)(ws + V1_F + i * 288 + (gq + 8) * 18);
                float2 xa = v0p[t], xb = v0p[t + 4];
                float2 ya = v1p[t], yb = v1p[t + 4];
                unsigned a0 = packh(h0 * xa.x, h0 * xa.y);
                unsigned a1 = packh(h1 * ya.x, h1 * ya.y);
                unsigned a2 = packh(h0 * xb.x, h0 * xb.y);
                unsigned a3 = packh(h1 * yb.x, h1 * yb.y);
                const uint2* bp = Bq + kc * 2 * 32 + lane;
                #pragma unroll
                for (int nb = 0; nb < 2; nb++) {
                    uint2 bb = bp[nb * 32];
                    mma16816(aq[i][nb], a0, a1, a2, a3, bb.x, bb.y);
                }
            }
        }

        // ---- epilogue part 2: out_v[w][i] = C1*v2[i]*R1[w] + C2*s2*R2i[w] ----
        {
            float s2_0 = ws[S2_F + gq], s2_1 = ws[S2_F + gq + 8];
            float v20[3], v21[3];
            #pragma unroll
            for (int i = 0; i < 3; i++) {
                v20[i] = ws[V2_F + gq * 3 + i];
                v21[i] = ws[V2_F + (gq + 8) * 3 + i];
            }
            float* row0 = out + (size_t)(e0 + gq) * 80 + 32;
            float* row1 = out + (size_t)(e0 + gq + 8) * 80 + 32;
            #pragma unroll
            for (int nbv = 0; nbv < 2; nbv++) {
                int w = nbv * 8 + 2 * t;
                float R1a0 = ag[4 + nbv][0], R1b0 = ag[4 + nbv][1]; // row gq, cols w,w+1
                float R1a1 = ag[4 + nbv][2], R1b1 = ag[4 + nbv][3]; // row gq+8
                float o0[6], o1[6];
                #pragma unroll
                for (int i = 0; i < 3; i++) {
                    o0[i]     = fmaf(C1F * v20[i], R1a0, C2F * s2_0 * aq[i][nbv][0]);
                    o0[3 + i] = fmaf(C1F * v20[i], R1b0, C2F * s2_0 * aq[i][nbv][1]);
                    o1[i]     = fmaf(C1F * v21[i], R1a1, C2F * s2_1 * aq[i][nbv][2]);
                    o1[3 + i] = fmaf(C1F * v21[i], R1b1, C2F * s2_1 * aq[i][nbv][3]);
                }
                #pragma unroll
                for (int j = 0; j < 3; j++) {
                    *(float2*)(row0 + 3 * w + 2 * j) = make_float2(o0[2*j], o0[2*j+1]);
                    *(float2*)(row1 + 3 * w + 2 * j) = make_float2(o1[2*j], o1[2*j+1]);
                }
            }
        }
    }
}

// Host-side exact replication of the reference silu normalization constant.
static float compute_silu_c()
{
    const int N = 200001;
    const double dx = 24.0 / 200000.0;
    const double inv_sqrt_2pi = 0.3989422804014326779;
    double acc = 0.0, prev = 0.0;
    for (int i = 0; i < N; i++) {
        double x = -12.0 + dx * (double)i;
        double pdf = exp(-0.5 * x * x) * inv_sqrt_2pi;
        double s = x / (1.0 + exp(-x));
        double y = s * s * pdf;
        if (i > 0) acc += 0.5 * (y + prev) * dx;
        prev = y;
    }
    return (float)(1.0 / sqrt(acc));
}

extern "C" void kernel_launch(void* const* d_in, const int* in_sizes, int n_in,
                              void* d_out, int out_size)
{
    const float* feature = (const float*)d_in[0];
    const int*   edge    = (const int*)  d_in[1];
    const float* ele     = (const float*)d_in[2];
    const float* esh     = (const float*)d_in[3];
    const float* fw1     = (const float*)d_in[4];
    const float* fw2     = (const float*)d_in[5];
    float* out = (float*)d_out;

    float silu_c = compute_silu_c();

    cudaFuncSetAttribute(tp_mma_kernel,
                         cudaFuncAttributeMaxDynamicSharedMemorySize, SMEM_TOTAL);

    zero_ticket_k<<<1, 1>>>();
    tp_mma_kernel<<<148, 512, SMEM_TOTAL>>>(feature, edge, ele, esh, fw1, fw2,
                                            out, silu_c);
}

// round 4
// speedup vs baseline: 8.2224x; 1.9108x over previous
#include <cuda_runtime.h>
#include <cuda_fp16.h>
#include <math.h>

#define N_EDGES_C 100000
#define NTILES    (N_EDGES_C / 16)   // 6250 exact

// e3nn constants: C0=C1=C2=1/sqrt(48), C3=0.25
#define C0F 0.14433756729740643f
#define C1F 0.14433756729740643f
#define C2F 0.14433756729740643f
#define C3F 0.25f

// ---- smem layout (bytes) ----
#define SW1_OFF   0                       // 160 floats = 640 B
#define BG_OFF    1024                    // uint4[32*3*32] = 49152 B
#define BP_OFF    (BG_OFF + 49152)        // uint4[16*2*32] = 16384 B
#define BQ_OFF    (BP_OFF + 16384)        // uint4[16*1*32] =  8192 B
#define WS_OFF    (BQ_OFF + 8192)         // 74752
#define WS_STRIDE 5120
// per-warp offsets (bytes within ws)
#define HD_B   0      // unsigned[16*17]  hdup[m*17+kh]            1088
#define S1_B   1088   // unsigned[16*17]  s1 pairs [m*17+p]        1088
#define V1_B   2176   // half[3*16*20]    v1h[i*320+m*20+u]        1920
#define BH_B   4096   // half[16*20]      b[m*20+u]                 640
#define S2_B   4736   // float[16]                                   64
#define V2_B   4800   // float[48]                                  192
#define SMEM_TOTAL (WS_OFF + 16 * WS_STRIDE)   // 156,672 B

__device__ unsigned int g_ticket;
__global__ void zero_ticket_k() { g_ticket = 0u; }

__device__ __forceinline__ unsigned packh(float lo, float hi) {
    unsigned r;
    asm("cvt.rn.f16x2.f32 %0, %1, %2;" : "=r"(r) : "f"(hi), "f"(lo));
    return r;
}
__device__ __forceinline__ unsigned h2u(__half2 h) { return *(unsigned*)&h; }
__device__ __forceinline__ __half2  u2h(unsigned u) { return *(__half2*)&u; }

__device__ __forceinline__ void mma16816(float* d,
    unsigned a0, unsigned a1, unsigned a2, unsigned a3,
    unsigned b0, unsigned b1)
{
    asm volatile(
      "mma.sync.aligned.m16n8k16.row.col.f32.f16.f16.f32 "
      "{%0,%1,%2,%3},{%4,%5,%6,%7},{%8,%9},{%0,%1,%2,%3};"
      : "+f"(d[0]), "+f"(d[1]), "+f"(d[2]), "+f"(d[3])
      : "r"(a0), "r"(a1), "r"(a2), "r"(a3), "r"(b0), "r"(b1));
}

__global__ __launch_bounds__(512, 1)
void tp_mma2_kernel(const float* __restrict__ feature,
                    const int*   __restrict__ edge,
                    const float* __restrict__ ele,
                    const float* __restrict__ esh,
                    const float* __restrict__ fw1,
                    const float* __restrict__ fw2,
                    float*       __restrict__ out,
                    float silu_c)
{
    extern __shared__ char smem[];
    float* sW1 = (float*)(smem + SW1_OFF);
    uint4* BG4 = (uint4*)(smem + BG_OFF);
    uint4* BP4 = (uint4*)(smem + BP_OFF);
    uint4* BQ4 = (uint4*)(smem + BQ_OFF);

    const int tid  = threadIdx.x;
    const int lane = tid & 31;
    const int warp = tid >> 5;
    const int gq   = lane >> 2;
    const int t    = lane & 3;

    // ================= prologue: stage fc_w1 + fragment-major B (uint4) ============
    {
        const float inb = 0.31622776601683794f; // 1/sqrt(10)
        for (int i = tid; i < 160; i += 512) sW1[i] = fw1[i] * inb;

        for (int i = tid; i < 4608; i += 512) {
            int li = i & 31, gg = li >> 2, tt = li & 3;
            float va[4], vb[4];
            if (i < 3072) {                 // BG: mm = kc*3 + p  (W0|W1, K=512)
                int mm = i >> 5;
                int kc = mm / 3, p = mm % 3;
                int k0 = kc * 16;
                int c0 = (2 * p) * 8 + gg, c1 = c0 + 8;
                int ks[4] = {k0 + 2*tt, k0 + 2*tt + 1, k0 + 2*tt + 8, k0 + 2*tt + 9};
                #pragma unroll
                for (int j = 0; j < 4; j++) {
                    int k = ks[j], kh = k >> 5, u = k & 31;
                    va[j] = 0.25f * (c0 < 32 ? fw2[kh*2304 + u*32 + c0]
                                             : fw2[kh*2304 + 1024 + u*16 + (c0-32)]);
                    vb[j] = 0.25f * (c1 < 32 ? fw2[kh*2304 + u*32 + c1]
                                             : fw2[kh*2304 + 1024 + u*16 + (c1-32)]);
                }
                BG4[mm * 32 + li] = make_uint4(packh(va[0],va[1]), packh(va[2],va[3]),
                                               packh(vb[0],vb[1]), packh(vb[2],vb[3]));
            } else if (i < 4096) {          // BP: W3 block, K=256
                int ii = i - 3072;
                int mm = ii >> 5;
                int kc = mm >> 1, p = mm & 1;
                int k0 = kc * 16;
                int c0 = (2 * p) * 8 + gg, c1 = c0 + 8;
                int ks[4] = {k0 + 2*tt, k0 + 2*tt + 1, k0 + 2*tt + 8, k0 + 2*tt + 9};
                #pragma unroll
                for (int j = 0; j < 4; j++) {
                    int k = ks[j], kh = k >> 4, u = k & 15;
                    va[j] = 0.25f * fw2[kh*2304 + 1792 + u*32 + c0];
                    vb[j] = 0.25f * fw2[kh*2304 + 1792 + u*32 + c1];
                }
                BP4[ii & ~31 | li] = make_uint4(packh(va[0],va[1]), packh(va[2],va[3]),
                                                packh(vb[0],vb[1]), packh(vb[2],vb[3]));
            } else {                        // BQ: W2 block, K=256, N=16
                int ii = i - 4096;
                int kc = ii >> 5;
                int k0 = kc * 16;
                int c0 = gg, c1 = 8 + gg;
                int ks[4] = {k0 + 2*tt, k0 + 2*tt + 1, k0 + 2*tt + 8, k0 + 2*tt + 9};
                #pragma unroll
                for (int j = 0; j < 4; j++) {
                    int k = ks[j], kh = k >> 4, u = k & 15;
                    va[j] = 0.25f * fw2[kh*2304 + 1536 + u*16 + c0];
                    vb[j] = 0.25f * fw2[kh*2304 + 1536 + u*16 + c1];
                }
                BQ4[ii] = make_uint4(packh(va[0],va[1]), packh(va[2],va[3]),
                                     packh(vb[0],vb[1]), packh(vb[2],vb[3]));
            }
        }
    }
    __syncthreads();

    char* wsb = smem + WS_OFF + warp * WS_STRIDE;
    unsigned* wsHD  = (unsigned*)(wsb + HD_B);
    unsigned* wsS1  = (unsigned*)(wsb + S1_B);
    __half*   wsV1h = (__half*)  (wsb + V1_B);
    __half*   wsBHh = (__half*)  (wsb + BH_B);
    float*    wsS2  = (float*)   (wsb + S2_B);
    float*    wsV2  = (float*)   (wsb + V2_B);

    // hoisted per-warp fragment pointers
    const unsigned* HD0 = wsHD + gq * 17;
    const unsigned* HD1 = wsHD + (gq + 8) * 17;
    const unsigned* S10 = wsS1 + gq * 17;
    const unsigned* S11 = wsS1 + (gq + 8) * 17;
    const unsigned* V1u = (const unsigned*)wsV1h;   // idx: i*160 + m*10 + q
    const unsigned* BHu = (const unsigned*)wsBHh;   // idx: m*10 + q
    const uint4* BGl = BG4 + lane;
    const uint4* BPl = BP4 + lane;
    const uint4* BQl = BQ4 + lane;

    // ================= per-warp tile loop (atomic ticket) ================
    for (;;) {
        unsigned tile;
        if (lane == 0) tile = atomicAdd(&g_ticket, 1u);
        tile = __shfl_sync(0xFFFFFFFFu, tile, 0);
        if (tile >= NTILES) break;
        const int e0 = (int)tile * 16;

        // ---- stage esh + read dst into regs ----
        int dreg = 0;
        if (lane < 16) {
            float4 q4 = ((const float4*)esh)[e0 + lane];
            wsS2[lane] = q4.x;
            wsV2[lane * 3 + 0] = q4.y;
            wsV2[lane * 3 + 1] = q4.z;
            wsV2[lane * 3 + 2] = q4.w;
            dreg = edge[N_EDGES_C + e0 + lane];
        }

        // ---- h (fp32 math, stored dup-packed fp16x2) ----
        {
            int m = lane & 15, halfi = lane >> 4;
            const float2* er2 = (const float2*)(ele + (size_t)(e0 + m) * 10);
            float x[10];
            #pragma unroll
            for (int j = 0; j < 5; j++) { float2 v = er2[j]; x[2*j] = v.x; x[2*j+1] = v.y; }
            #pragma unroll
            for (int j = 0; j < 8; j++) {
                int kh = halfi * 8 + j;
                float a = 0.f;
                #pragma unroll
                for (int r = 0; r < 10; r++) a = fmaf(x[r], sW1[r * 16 + kh], a);
                float sg = 1.0f / (1.0f + __expf(-a));
                wsHD[m * 17 + kh] = h2u(__float2half2_rn(silu_c * a * sg));
            }
        }

        // ---- feature gather, high MLP (20 independent LDG.64) ----
        #pragma unroll
        for (int it = 0; it < 20; it++) {
            int idx = it * 32 + lane;
            int m = idx / 40;
            int c = idx - m * 40;          // float2 granule within 80-float row
            int dst = __shfl_sync(0xFFFFFFFFu, dreg, m);
            float2 f = ((const float2*)(feature + (size_t)dst * 80))[c];
            if (c < 16) {
                wsS1[m * 17 + c] = h2u(__floats2half2_rn(f.x, f.y));
            } else {
                int j0 = 2 * c - 32;
                wsV1h[(j0 % 3) * 320 + m * 20 + (j0 / 3)] = __float2half(f.x);
                int j1 = j0 + 1;
                wsV1h[(j1 % 3) * 320 + m * 20 + (j1 / 3)] = __float2half(f.y);
            }
        }
        __syncwarp();

        // ---- b[m][u] = v1 . v2 (fp16 store) ----
        {
            int m = lane >> 1, ub = (lane & 1) * 8;
            float w2x = wsV2[m*3+0], w2y = wsV2[m*3+1], w2z = wsV2[m*3+2];
            #pragma unroll
            for (int j = 0; j < 8; j++) {
                int u = ub + j;
                float vx = __half2float(wsV1h[0*320 + m*20 + u]);
                float vy = __half2float(wsV1h[1*320 + m*20 + u]);
                float vz = __half2float(wsV1h[2*320 + m*20 + u]);
                wsBHh[m * 20 + u] = __float2half(fmaf(vx, w2x, fmaf(vy, w2y, vz * w2z)));
            }
        }
        __syncwarp();

        // ================ GEMM 1: g = h(x)s1, N=48 (R0|R1) ================
        float ag[6][4];
        #pragma unroll
        for (int nb = 0; nb < 6; nb++) { ag[nb][0]=0.f; ag[nb][1]=0.f; ag[nb][2]=0.f; ag[nb][3]=0.f; }

        #pragma unroll
        for (int kc = 0; kc < 32; kc++) {
            int kh = kc >> 1, p0 = (kc & 1) * 8;
            __half2 h0 = u2h(HD0[kh]), h1 = u2h(HD1[kh]);
            __half2 xa = u2h(S10[p0 + t]), xb = u2h(S10[p0 + t + 4]);
            __half2 ya = u2h(S11[p0 + t]), yb = u2h(S11[p0 + t + 4]);
            unsigned a0 = h2u(__hmul2(h0, xa)), a1 = h2u(__hmul2(h1, ya));
            unsigned a2 = h2u(__hmul2(h0, xb)), a3 = h2u(__hmul2(h1, yb));
            #pragma unroll
            for (int p = 0; p < 3; p++) {
                uint4 bb = BGl[kc * 96 + p * 32];
                mma16816(ag[2*p],   a0, a1, a2, a3, bb.x, bb.y);
                mma16816(ag[2*p+1], a0, a1, a2, a3, bb.z, bb.w);
            }
        }

        // ================ GEMM 2: p = h(x)b, N=32 (R3) ================
        float ap[4][4];
        #pragma unroll
        for (int nb = 0; nb < 4; nb++) { ap[nb][0]=0.f; ap[nb][1]=0.f; ap[nb][2]=0.f; ap[nb][3]=0.f; }

        #pragma unroll
        for (int kc = 0; kc < 16; kc++) {
            __half2 h0 = u2h(HD0[kc]), h1 = u2h(HD1[kc]);
            __half2 xa = u2h(BHu[gq*10 + t]),     xb = u2h(BHu[gq*10 + t + 4]);
            __half2 ya = u2h(BHu[(gq+8)*10 + t]), yb = u2h(BHu[(gq+8)*10 + t + 4]);
            unsigned a0 = h2u(__hmul2(h0, xa)), a1 = h2u(__hmul2(h1, ya));
            unsigned a2 = h2u(__hmul2(h0, xb)), a3 = h2u(__hmul2(h1, yb));
            #pragma unroll
            for (int p = 0; p < 2; p++) {
                uint4 bb = BPl[kc * 64 + p * 32];
                mma16816(ap[2*p],   a0, a1, a2, a3, bb.x, bb.y);
                mma16816(ap[2*p+1], a0, a1, a2, a3, bb.z, bb.w);
            }
        }

        // ---- epilogue 1: out_s = C0*s2*R0 + C3*R3 ----
        {
            float s2_0 = wsS2[gq], s2_1 = wsS2[gq + 8];
            float* row0 = out + (size_t)(e0 + gq) * 80;
            float* row1 = out + (size_t)(e0 + gq + 8) * 80;
            #pragma unroll
            for (int nb = 0; nb < 4; nb++) {
                int w = nb * 8 + 2 * t;
                float2 o0, o1;
                o0.x = fmaf(C0F * s2_0, ag[nb][0], C3F * ap[nb][0]);
                o0.y = fmaf(C0F * s2_0, ag[nb][1], C3F * ap[nb][1]);
                o1.x = fmaf(C0F * s2_1, ag[nb][2], C3F * ap[nb][2]);
                o1.y = fmaf(C0F * s2_1, ag[nb][3], C3F * ap[nb][3]);
                *(float2*)(row0 + w) = o0;
                *(float2*)(row1 + w) = o1;
            }
        }

        // ================ GEMM 3: q_i = h(x)v1_i, N=16 each (R2i) ================
        float aq[3][2][4];
        #pragma unroll
        for (int i = 0; i < 3; i++)
            #pragma unroll
            for (int nb = 0; nb < 2; nb++) { aq[i][nb][0]=0.f; aq[i][nb][1]=0.f; aq[i][nb][2]=0.f; aq[i][nb][3]=0.f; }

        #pragma unroll
        for (int kc = 0; kc < 16; kc++) {
            __half2 h0 = u2h(HD0[kc]), h1 = u2h(HD1[kc]);
            #pragma unroll
            for (int i = 0; i < 3; i++) {
                __half2 xa = u2h(V1u[i*160 + gq*10 + t]),     xb = u2h(V1u[i*160 + gq*10 + t + 4]);
                __half2 ya = u2h(V1u[i*160 + (gq+8)*10 + t]), yb = u2h(V1u[i*160 + (gq+8)*10 + t + 4]);
                unsigned a0 = h2u(__hmul2(h0, xa)), a1 = h2u(__hmul2(h1, ya));
                unsigned a2 = h2u(__hmul2(h0, xb)), a3 = h2u(__hmul2(h1, yb));
                uint4 bb = BQl[kc * 32];
                mma16816(aq[i][0], a0, a1, a2, a3, bb.x, bb.y);
                mma16816(aq[i][1], a0, a1, a2, a3, bb.z, bb.w);
            }
        }

        // ---- epilogue 2: out_v[w][i] = C1*v2[i]*R1[w] + C2*s2*R2i[w] ----
        {
            float s2_0 = wsS2[gq], s2_1 = wsS2[gq + 8];
            float v20[3], v21[3];
            #pragma unroll
            for (int i = 0; i < 3; i++) {
                v20[i] = wsV2[gq * 3 + i];
                v21[i] = wsV2[(gq + 8) * 3 + i];
            }
            float* row0 = out + (size_t)(e0 + gq) * 80 + 32;
            float* row1 = out + (size_t)(e0 + gq + 8) * 80 + 32;
            #pragma unroll
            for (int nbv = 0; nbv < 2; nbv++) {
                int w = nbv * 8 + 2 * t;
                float R1a0 = ag[4 + nbv][0], R1b0 = ag[4 + nbv][1];
                float R1a1 = ag[4 + nbv][2], R1b1 = ag[4 + nbv][3];
                float o0[6], o1[6];
                #pragma unroll
                for (int i = 0; i < 3; i++) {
                    o0[i]     = fmaf(C1F * v20[i], R1a0, C2F * s2_0 * aq[i][nbv][0]);
                    o0[3 + i] = fmaf(C1F * v20[i], R1b0, C2F * s2_0 * aq[i][nbv][1]);
                    o1[i]     = fmaf(C1F * v21[i], R1a1, C2F * s2_1 * aq[i][nbv][2]);
                    o1[3 + i] = fmaf(C1F * v21[i], R1b1, C2F * s2_1 * aq[i][nbv][3]);
                }
                #pragma unroll
                for (int j = 0; j < 3; j++) {
                    *(float2*)(row0 + 3 * w + 2 * j) = make_float2(o0[2*j], o0[2*j+1]);
                    *(float2*)(row1 + 3 * w + 2 * j) = make_float2(o1[2*j], o1[2*j+1]);
                }
            }
        }
    }
}

// Host-side exact replication of the reference silu normalization constant.
static float compute_silu_c()
{
    const int N = 200001;
    const double dx = 24.0 / 200000.0;
    const double inv_sqrt_2pi = 0.3989422804014326779;
    double acc = 0.0, prev = 0.0;
    for (int i = 0; i < N; i++) {
        double x = -12.0 + dx * (double)i;
        double pdf = exp(-0.5 * x * x) * inv_sqrt_2pi;
        double s = x / (1.0 + exp(-x));
        double y = s * s * pdf;
        if (i > 0) acc += 0.5 * (y + prev) * dx;
        prev = y;
    }
    return (float)(1.0 / sqrt(acc));
}

extern "C" void kernel_launch(void* const* d_in, const int* in_sizes, int n_in,
                              void* d_out, int out_size)
{
    const float* feature = (const float*)d_in[0];
    const int*   edge    = (const int*)  d_in[1];
    const float* ele     = (const float*)d_in[2];
    const float* esh     = (const float*)d_in[3];
    const float* fw1     = (const float*)d_in[4];
    const float* fw2     = (const float*)d_in[5];
    float* out = (float*)d_out;

    float silu_c = compute_silu_c();

    cudaFuncSetAttribute(tp_mma2_kernel,
                         cudaFuncAttributeMaxDynamicSharedMemorySize, SMEM_TOTAL);

    zero_ticket_k<<<1, 1>>>();
    tp_mma2_kernel<<<148, 512, SMEM_TOTAL>>>(feature, edge, ele, esh, fw1, fw2,
                                             out, silu_c);
}